// round 2
// baseline (speedup 1.0000x reference)
#include <cuda_runtime.h>
#include <cstdint>

// ---------------- problem constants ----------------
#define BB      8
#define HEADS   4
#define NQ      3136
#define NKV     784
#define DH      32      // head dim
#define CC      128
#define TQ      128     // queries per CTA (attention)
#define TK      56      // kv tile (784 = 14*56)

typedef unsigned long long u64;

// ---------------- scratch (device globals; no allocation) ----------------
__device__ float g_q [BB * HEADS * NQ  * DH];   // (B,H,N,32)
__device__ float g_k [BB * HEADS * NKV * DH];   // (B,H,Nkv,32)
__device__ float g_v [BB * HEADS * NKV * DH];
__device__ float g_xr[BB * NKV * CC];           // spatially reduced tokens
__device__ float g_ao[BB * NQ  * CC];           // attention output (B,N,C)

// ---------------- f32x2 packed helpers (Blackwell FFMA2) ----------------
__device__ __forceinline__ u64 pack2(float x, float y) {
    u64 r; asm("mov.b64 %0, {%1, %2};" : "=l"(r) : "f"(x), "f"(y)); return r;
}
__device__ __forceinline__ void unpack2(u64 v, float& x, float& y) {
    asm("mov.b64 {%0, %1}, %2;" : "=f"(x), "=f"(y) : "l"(v));
}
__device__ __forceinline__ u64 fma2(u64 a, u64 b, u64 c) {
    u64 d; asm("fma.rn.f32x2 %0, %1, %2, %3;" : "=l"(d) : "l"(a), "l"(b), "l"(c)); return d;
}
__device__ __forceinline__ u64 mul2(u64 a, u64 b) {
    u64 d; asm("mul.rn.f32x2 %0, %1, %2;" : "=l"(d) : "l"(a), "l"(b)); return d;
}

// ---------------- projection GEMM body: Y = X(Mx128) @ W(128x128) + b ------
// CTA tile 64 rows x 128 cols. Thread tile 8 rows x 4 cols, rows packed in
// f32x2 pairs (Xs transposed so a row-pair is one broadcast LDS.64).
__device__ __forceinline__ void proj_body(
    const float* __restrict__ X, const float* __restrict__ W,
    const float* __restrict__ bias, float* __restrict__ Y,
    int rowb, int M, int RPB, int swizzle)
{
    __shared__ __align__(16) float Xs[32][66];    // [k][row], pad 2
    __shared__ __align__(16) float Ws[32][128];

    const int tid   = threadIdx.x;
    const int col_t = tid & 31;   // 0..31 -> 4 cols each
    const int row_t = tid >> 5;   // 0..7  -> 8 rows each

    u64 acc2[4][4];               // [rowpair][col]
#pragma unroll
    for (int rp = 0; rp < 4; rp++)
#pragma unroll
        for (int c = 0; c < 4; c++) acc2[rp][c] = 0ULL;

    for (int kc = 0; kc < 128; kc += 32) {
        __syncthreads();
#pragma unroll
        for (int i = 0; i < 8; i++) {          // X tile: 64 rows x 32 k
            int idx = tid + i * 256;
            int r = idx >> 5, kk = idx & 31;
            Xs[kk][r] = X[(size_t)(rowb + r) * CC + kc + kk];
        }
#pragma unroll
        for (int i = 0; i < 16; i++) {         // W tile: 32 k x 128 cols
            int idx = tid + i * 256;
            int kk = idx >> 7, cc2 = idx & 127;
            Ws[kk][cc2] = W[(size_t)(kc + kk) * CC + cc2];
        }
        __syncthreads();
#pragma unroll
        for (int kk = 0; kk < 32; kk++) {
            float4 wv = *(const float4*)&Ws[kk][col_t * 4];
            u64 wd0 = pack2(wv.x, wv.x);
            u64 wd1 = pack2(wv.y, wv.y);
            u64 wd2 = pack2(wv.z, wv.z);
            u64 wd3 = pack2(wv.w, wv.w);
            const u64* xrow = (const u64*)&Xs[kk][row_t * 8];
#pragma unroll
            for (int rp = 0; rp < 4; rp++) {
                u64 xp = xrow[rp];             // rows (2rp, 2rp+1) packed
                acc2[rp][0] = fma2(xp, wd0, acc2[rp][0]);
                acc2[rp][1] = fma2(xp, wd1, acc2[rp][1]);
                acc2[rp][2] = fma2(xp, wd2, acc2[rp][2]);
                acc2[rp][3] = fma2(xp, wd3, acc2[rp][3]);
            }
        }
    }

    const int col0 = col_t * 4;
    float4 bv = *(const float4*)&bias[col0];
#pragma unroll
    for (int rp = 0; rp < 4; rp++) {
        float lo[4], hi[4];
#pragma unroll
        for (int c = 0; c < 4; c++) unpack2(acc2[rp][c], lo[c], hi[c]);
        int row0 = rowb + row_t * 8 + 2 * rp;
#pragma unroll
        for (int half = 0; half < 2; half++) {
            int row = row0 + half;
            if (row >= M) continue;
            float* s = half ? hi : lo;
            float4 o;
            o.x = s[0] + bv.x; o.y = s[1] + bv.y;
            o.z = s[2] + bv.z; o.w = s[3] + bv.w;
            if (swizzle) {
                int b = row / RPB, n = row % RPB;
                int h = col0 >> 5, d = col0 & 31;
                *(float4*)&Y[(((size_t)(b * HEADS + h) * RPB + n)) * DH + d] = o;
            } else {
                *(float4*)&Y[(size_t)row * CC + col0] = o;
            }
        }
    }
}

__global__ __launch_bounds__(256) void proj_kernel(
    const float* __restrict__ X, const float* __restrict__ W,
    const float* __restrict__ bias, float* __restrict__ Y,
    int M, int RPB, int swizzle)
{
    proj_body(X, W, bias, Y, blockIdx.x * 64, M, RPB, swizzle);
}

// fused k+v projections: first half of grid does K, second half does V
__global__ __launch_bounds__(256) void proj_kv_kernel(
    const float* __restrict__ X,
    const float* __restrict__ Wk, const float* __restrict__ bk, float* __restrict__ K,
    const float* __restrict__ Wv, const float* __restrict__ bv, float* __restrict__ V,
    int M, int RPB)
{
    int nb = gridDim.x >> 1;
    int half = blockIdx.x >= nb;
    int rowb = (blockIdx.x - (half ? nb : 0)) * 64;
    if (half) proj_body(X, Wv, bv, V, rowb, M, RPB, 1);
    else      proj_body(X, Wk, bk, K, rowb, M, RPB, 1);
}

// ---------------- spatial reduction: depthwise 2x2 stride-2 conv + BN ------
__global__ void sr_conv_kernel(
    const float* __restrict__ x, const float* __restrict__ cw, const float* __restrict__ cb,
    const float* __restrict__ gamma, const float* __restrict__ beta,
    const float* __restrict__ mean, const float* __restrict__ var,
    float* __restrict__ xr)
{
    int t = blockIdx.x * blockDim.x + threadIdx.x;
    if (t >= BB * NKV * CC) return;
    int c = t & (CC - 1);
    int p = (t >> 7) % NKV;
    int b = t / (NKV * CC);
    int oy = p / 28, ox = p % 28;

    const float* xb = x + (size_t)b * NQ * CC;
    float s = 0.f;
#pragma unroll
    for (int i = 0; i < 2; i++)
#pragma unroll
        for (int j = 0; j < 2; j++)
            s += xb[(size_t)((2 * oy + i) * 56 + (2 * ox + j)) * CC + c] * cw[c * 4 + i * 2 + j];
    s += cb[c];
    float iv = gamma[c] * rsqrtf(var[c] + 1e-5f);
    xr[t] = s * iv + (beta[c] - mean[c] * iv);
}

// ---------------- fused flash attention --------------------------------
// One (b,h,128-query tile) per CTA, 1 query/thread. kv processed in chunks
// of 8: 8 independent score chains (ILP), one batched max/rescale per chunk.
__global__ __launch_bounds__(128) void attn_kernel(
    const float* __restrict__ q, const float* __restrict__ k, const float* __restrict__ v,
    const float* __restrict__ relpos, float* __restrict__ out)
{
    __shared__ __align__(16) float Ks[TK][DH];
    __shared__ __align__(16) float Vs[TK][DH];
    __shared__ float Bsm[TQ][TK + 1];   // stride 57 -> conflict-free column reads

    const int b  = blockIdx.z;
    const int h  = blockIdx.y;
    const int qt = blockIdx.x;
    const int tid = threadIdx.x;
    const int n = qt * TQ + tid;
    const bool valid = (n < NQ);
    const float scale = 0.17677669529663687f;  // 32^-0.5

    // load q row (pre-scaled), packed as 16 f32x2
    u64 ql2[16];
    {
        const float* qrow = q + ((size_t)(b * HEADS + h) * NQ + (valid ? n : 0)) * DH;
#pragma unroll
        for (int i = 0; i < 8; i++) {
            float4 t4 = *(const float4*)(qrow + i * 4);
            ql2[2 * i]     = pack2(t4.x * scale, t4.y * scale);
            ql2[2 * i + 1] = pack2(t4.z * scale, t4.w * scale);
        }
    }

    float m = -1e30f, l = 0.f;
    u64 acc2[16];
#pragma unroll
    for (int i = 0; i < 16; i++) acc2[i] = 0ULL;

    const float* kb = k + (size_t)(b * HEADS + h) * NKV * DH;
    const float* vb = v + (size_t)(b * HEADS + h) * NKV * DH;
    const float* rp = relpos + (size_t)h * NQ * NKV;
    const int qbase = qt * TQ;

    for (int kt = 0; kt < NKV; kt += TK) {
        __syncthreads();
        // cooperative K/V tile load (coalesced)
#pragma unroll 2
        for (int idx = tid; idx < TK * DH; idx += 128) {
            int r = idx >> 5, d = idx & 31;
            Ks[r][d] = kb[(size_t)(kt + r) * DH + d];
            Vs[r][d] = vb[(size_t)(kt + r) * DH + d];
        }
        // cooperative bias tile load (coalesced); incremental div-free indexing
        {
            int r = tid / TK, c = tid % TK;
#pragma unroll 1
            for (int it = 0; it < TK; it++) {      // 128*56/128 = 56 iterations
                int qn = qbase + r;
                Bsm[r][c] = (qn < NQ) ? rp[(size_t)qn * NKV + kt + c] : 0.f;
                r += 2; c += 16;
                if (c >= TK) { c -= TK; r += 1; }
            }
        }
        __syncthreads();

        if (valid) {
#pragma unroll 1
            for (int c0 = 0; c0 < TK; c0 += 8) {
                // ---- 8 independent score chains ----
                u64 s2[8];
#pragma unroll
                for (int j = 0; j < 8; j++) s2[j] = pack2(Bsm[tid][c0 + j], 0.f);
#pragma unroll
                for (int i2 = 0; i2 < 8; i2++) {
#pragma unroll
                    for (int j = 0; j < 8; j++) {
                        ulonglong2 kk2 = ((const ulonglong2*)Ks[c0 + j])[i2];
                        s2[j] = fma2(ql2[2 * i2],     kk2.x, s2[j]);
                        s2[j] = fma2(ql2[2 * i2 + 1], kk2.y, s2[j]);
                    }
                }
                float sc[8];
#pragma unroll
                for (int j = 0; j < 8; j++) {
                    float a, bb2; unpack2(s2[j], a, bb2);
                    sc[j] = a + bb2;
                }
                // ---- batched online softmax update ----
                float cmax = sc[0];
#pragma unroll
                for (int j = 1; j < 8; j++) cmax = fmaxf(cmax, sc[j]);
                float newm = fmaxf(m, cmax);
                float corr = __expf(m - newm);
                l *= corr;
                u64 c2 = pack2(corr, corr);
#pragma unroll
                for (int i = 0; i < 16; i++) acc2[i] = mul2(acc2[i], c2);
                m = newm;
                float p[8];
#pragma unroll
                for (int j = 0; j < 8; j++) { p[j] = __expf(sc[j] - m); l += p[j]; }
                // ---- accumulate P @ V ----
#pragma unroll
                for (int j = 0; j < 8; j++) {
                    u64 p2 = pack2(p[j], p[j]);
                    const ulonglong2* vrow = (const ulonglong2*)Vs[c0 + j];
#pragma unroll
                    for (int i2 = 0; i2 < 8; i2++) {
                        ulonglong2 vv = vrow[i2];
                        acc2[2 * i2]     = fma2(p2, vv.x, acc2[2 * i2]);
                        acc2[2 * i2 + 1] = fma2(p2, vv.y, acc2[2 * i2 + 1]);
                    }
                }
            }
        }
    }

    if (valid) {
        float inv = 1.f / l;
        float* orow = out + ((size_t)(b * NQ + n)) * CC + h * DH;
#pragma unroll
        for (int i = 0; i < 8; i++) {
            float x0, x1, x2, x3;
            unpack2(acc2[2 * i], x0, x1);
            unpack2(acc2[2 * i + 1], x2, x3);
            float4 o; o.x = x0 * inv; o.y = x1 * inv; o.z = x2 * inv; o.w = x3 * inv;
            *(float4*)(orow + i * 4) = o;
        }
    }
}

// ---------------- launch ----------------
extern "C" void kernel_launch(void* const* d_in, const int* in_sizes, int n_in,
                              void* d_out, int out_size)
{
    const float* x      = (const float*)d_in[0];
    const float* relpos = (const float*)d_in[1];
    const float* Wq     = (const float*)d_in[2];
    const float* bq     = (const float*)d_in[3];
    const float* Wk     = (const float*)d_in[4];
    const float* bk     = (const float*)d_in[5];
    const float* Wv     = (const float*)d_in[6];
    const float* bv     = (const float*)d_in[7];
    const float* cw     = (const float*)d_in[8];
    const float* cb     = (const float*)d_in[9];
    const float* gamma  = (const float*)d_in[10];
    const float* beta   = (const float*)d_in[11];
    const float* mean   = (const float*)d_in[12];
    const float* var    = (const float*)d_in[13];
    const float* Wp     = (const float*)d_in[14];
    const float* bp     = (const float*)d_in[15];
    float* out = (float*)d_out;

    float *q, *k, *v, *xr, *ao;
    cudaGetSymbolAddress((void**)&q,  g_q);
    cudaGetSymbolAddress((void**)&k,  g_k);
    cudaGetSymbolAddress((void**)&v,  g_v);
    cudaGetSymbolAddress((void**)&xr, g_xr);
    cudaGetSymbolAddress((void**)&ao, g_ao);

    // 1) q projection (head-swizzled)
    proj_kernel<<<(BB * NQ) / 64, 256>>>(x, Wq, bq, q, BB * NQ, NQ, 1);
    // 2) spatial reduction conv + BN
    sr_conv_kernel<<<(BB * NKV * CC + 255) / 256, 256>>>(x, cw, cb, gamma, beta, mean, var, xr);
    // 3) fused k+v projections (head-swizzled), grid fills the chip
    proj_kv_kernel<<<2 * (BB * NKV) / 64, 256>>>(xr, Wk, bk, k, Wv, bv, v, BB * NKV, NKV);
    // 4) fused attention with online softmax
    dim3 ag((NQ + TQ - 1) / TQ, HEADS, BB);
    attn_kernel<<<ag, 128>>>(q, k, v, relpos, ao);
    // 5) output projection
    proj_kernel<<<(BB * NQ) / 64, 256>>>(ao, Wp, bp, out, BB * NQ, NQ, 0);
}

// round 3
// speedup vs baseline: 1.8729x; 1.8729x over previous
#include <cuda_runtime.h>
#include <cstdint>

// ---------------- problem constants ----------------
#define BB      8
#define HEADS   4
#define NQ      3136
#define NKV     784
#define DH      32      // head dim
#define CC      128
#define TQ      128     // queries per CTA (attention)
#define TK      56      // kv tile (784 = 14*56)
#define NTILES  (NKV / TK)

typedef unsigned long long u64;

// ---------------- scratch (device globals; no allocation) ----------------
__device__ float g_q [BB * HEADS * NQ  * DH];   // (B,H,N,32)
__device__ float g_k [BB * HEADS * NKV * DH];   // (B,H,Nkv,32)
__device__ float g_v [BB * HEADS * NKV * DH];
__device__ float g_xr[BB * NKV * CC];           // spatially reduced tokens
__device__ float g_ao[BB * NQ  * CC];           // attention output (B,N,C)

// ---------------- f32x2 packed helpers (Blackwell FFMA2) ----------------
__device__ __forceinline__ u64 pack2(float x, float y) {
    u64 r; asm("mov.b64 %0, {%1, %2};" : "=l"(r) : "f"(x), "f"(y)); return r;
}
__device__ __forceinline__ void unpack2(u64 v, float& x, float& y) {
    asm("mov.b64 {%0, %1}, %2;" : "=f"(x), "=f"(y) : "l"(v));
}
__device__ __forceinline__ u64 fma2(u64 a, u64 b, u64 c) {
    u64 d; asm("fma.rn.f32x2 %0, %1, %2, %3;" : "=l"(d) : "l"(a), "l"(b), "l"(c)); return d;
}
__device__ __forceinline__ u64 mul2(u64 a, u64 b) {
    u64 d; asm("mul.rn.f32x2 %0, %1, %2;" : "=l"(d) : "l"(a), "l"(b)); return d;
}

// ---------------- cp.async helpers ----------------
__device__ __forceinline__ unsigned smem_u32(const void* p) {
    return (unsigned)__cvta_generic_to_shared(p);
}
__device__ __forceinline__ void cp16(unsigned dst, const void* src) {
    asm volatile("cp.async.cg.shared.global [%0], [%1], 16;\n" :: "r"(dst), "l"(src));
}
__device__ __forceinline__ void cp_commit() {
    asm volatile("cp.async.commit_group;\n" ::: "memory");
}
__device__ __forceinline__ void cp_wait0() {
    asm volatile("cp.async.wait_group 0;\n" ::: "memory");
}

// ---------------- projection GEMM body: Y = X(Mx128) @ W(128x128) + b ------
__device__ __forceinline__ void proj_body(
    const float* __restrict__ X, const float* __restrict__ W,
    const float* __restrict__ bias, float* __restrict__ Y,
    int rowb, int M, int RPB, int swizzle)
{
    __shared__ __align__(16) float Xs[32][66];    // [k][row], pad 2
    __shared__ __align__(16) float Ws[32][128];

    const int tid   = threadIdx.x;
    const int col_t = tid & 31;   // 0..31 -> 4 cols each
    const int row_t = tid >> 5;   // 0..7  -> 8 rows each

    u64 acc2[4][4];               // [rowpair][col]
#pragma unroll
    for (int rp = 0; rp < 4; rp++)
#pragma unroll
        for (int c = 0; c < 4; c++) acc2[rp][c] = 0ULL;

    for (int kc = 0; kc < 128; kc += 32) {
        __syncthreads();
#pragma unroll
        for (int i = 0; i < 8; i++) {          // X tile: 64 rows x 32 k
            int idx = tid + i * 256;
            int r = idx >> 5, kk = idx & 31;
            Xs[kk][r] = X[(size_t)(rowb + r) * CC + kc + kk];
        }
#pragma unroll
        for (int i = 0; i < 16; i++) {         // W tile: 32 k x 128 cols
            int idx = tid + i * 256;
            int kk = idx >> 7, cc2 = idx & 127;
            Ws[kk][cc2] = W[(size_t)(kc + kk) * CC + cc2];
        }
        __syncthreads();
#pragma unroll
        for (int kk = 0; kk < 32; kk++) {
            float4 wv = *(const float4*)&Ws[kk][col_t * 4];
            u64 wd0 = pack2(wv.x, wv.x);
            u64 wd1 = pack2(wv.y, wv.y);
            u64 wd2 = pack2(wv.z, wv.z);
            u64 wd3 = pack2(wv.w, wv.w);
            const u64* xrow = (const u64*)&Xs[kk][row_t * 8];
#pragma unroll
            for (int rp = 0; rp < 4; rp++) {
                u64 xp = xrow[rp];
                acc2[rp][0] = fma2(xp, wd0, acc2[rp][0]);
                acc2[rp][1] = fma2(xp, wd1, acc2[rp][1]);
                acc2[rp][2] = fma2(xp, wd2, acc2[rp][2]);
                acc2[rp][3] = fma2(xp, wd3, acc2[rp][3]);
            }
        }
    }

    const int col0 = col_t * 4;
    float4 bv = *(const float4*)&bias[col0];
#pragma unroll
    for (int rp = 0; rp < 4; rp++) {
        float lo[4], hi[4];
#pragma unroll
        for (int c = 0; c < 4; c++) unpack2(acc2[rp][c], lo[c], hi[c]);
        int row0 = rowb + row_t * 8 + 2 * rp;
#pragma unroll
        for (int half = 0; half < 2; half++) {
            int row = row0 + half;
            if (row >= M) continue;
            float* s = half ? hi : lo;
            float4 o;
            o.x = s[0] + bv.x; o.y = s[1] + bv.y;
            o.z = s[2] + bv.z; o.w = s[3] + bv.w;
            if (swizzle) {
                int b = row / RPB, n = row % RPB;
                int h = col0 >> 5, d = col0 & 31;
                *(float4*)&Y[(((size_t)(b * HEADS + h) * RPB + n)) * DH + d] = o;
            } else {
                *(float4*)&Y[(size_t)row * CC + col0] = o;
            }
        }
    }
}

__global__ __launch_bounds__(256) void proj_kernel(
    const float* __restrict__ X, const float* __restrict__ W,
    const float* __restrict__ bias, float* __restrict__ Y,
    int M, int RPB, int swizzle)
{
    proj_body(X, W, bias, Y, blockIdx.x * 64, M, RPB, swizzle);
}

__global__ __launch_bounds__(256) void proj_kv_kernel(
    const float* __restrict__ X,
    const float* __restrict__ Wk, const float* __restrict__ bk, float* __restrict__ K,
    const float* __restrict__ Wv, const float* __restrict__ bv, float* __restrict__ V,
    int M, int RPB)
{
    int nb = gridDim.x >> 1;
    int half = blockIdx.x >= nb;
    int rowb = (blockIdx.x - (half ? nb : 0)) * 64;
    if (half) proj_body(X, Wv, bv, V, rowb, M, RPB, 1);
    else      proj_body(X, Wk, bk, K, rowb, M, RPB, 1);
}

// ---------------- spatial reduction: depthwise 2x2 stride-2 conv + BN ------
__global__ void sr_conv_kernel(
    const float* __restrict__ x, const float* __restrict__ cw, const float* __restrict__ cb,
    const float* __restrict__ gamma, const float* __restrict__ beta,
    const float* __restrict__ mean, const float* __restrict__ var,
    float* __restrict__ xr)
{
    int t = blockIdx.x * blockDim.x + threadIdx.x;
    if (t >= BB * NKV * CC) return;
    int c = t & (CC - 1);
    int p = (t >> 7) % NKV;
    int b = t / (NKV * CC);
    int oy = p / 28, ox = p % 28;

    const float* xb = x + (size_t)b * NQ * CC;
    float s = 0.f;
#pragma unroll
    for (int i = 0; i < 2; i++)
#pragma unroll
        for (int j = 0; j < 2; j++)
            s += xb[(size_t)((2 * oy + i) * 56 + (2 * ox + j)) * CC + c] * cw[c * 4 + i * 2 + j];
    s += cb[c];
    float iv = gamma[c] * rsqrtf(var[c] + 1e-5f);
    xr[t] = s * iv + (beta[c] - mean[c] * iv);
}

// ---------------- fused flash attention v3 --------------------------------
// 1 query/thread, 128 q/CTA. K/V double-buffered via cp.async; bias read
// directly from gmem (one 32B sector per lane per chunk), prefetched a chunk
// ahead. kv chunks of 8 with batched + conditional softmax rescale.
__global__ __launch_bounds__(128) void attn_kernel(
    const float* __restrict__ q, const float* __restrict__ k, const float* __restrict__ v,
    const float* __restrict__ relpos, float* __restrict__ out)
{
    __shared__ __align__(16) float Ks[2][TK][DH];
    __shared__ __align__(16) float Vs[2][TK][DH];

    const int b  = blockIdx.z;
    const int h  = blockIdx.y;
    const int qt = blockIdx.x;
    const int tid = threadIdx.x;
    const int n = qt * TQ + tid;
    const bool valid = (n < NQ);
    const int nc = valid ? n : (NQ - 1);
    const float scale = 0.17677669529663687f;  // 32^-0.5

    const float* kb = k + (size_t)(b * HEADS + h) * NKV * DH;
    const float* vb = v + (size_t)(b * HEADS + h) * NKV * DH;
    const float* rprow = relpos + (size_t)h * NQ * NKV + (size_t)nc * NKV;

    // load q row (pre-scaled), packed as 16 f32x2
    u64 ql2[16];
    {
        const float* qrow = q + ((size_t)(b * HEADS + h) * NQ + nc) * DH;
#pragma unroll
        for (int i = 0; i < 8; i++) {
            float4 t4 = *(const float4*)(qrow + i * 4);
            ql2[2 * i]     = pack2(t4.x * scale, t4.y * scale);
            ql2[2 * i + 1] = pack2(t4.z * scale, t4.w * scale);
        }
    }

    float m = -1e30f, l = 0.f;
    u64 acc2[16];
#pragma unroll
    for (int i = 0; i < 16; i++) acc2[i] = 0ULL;

    // ---- prefetch tile 0 (K/V via cp.async) ----
    // 56*32 floats = 448 x 16B per array; 128 threads -> 3.5 -> loop 4 w/ guard
#pragma unroll
    for (int i = 0; i < 4; i++) {
        int idx = tid + i * 128;
        if (idx < TK * DH / 4) {
            cp16(smem_u32(&Ks[0][0][0]) + idx * 16, kb + idx * 4);
            cp16(smem_u32(&Vs[0][0][0]) + idx * 16, vb + idx * 4);
        }
    }
    cp_commit();

    // ---- prefetch bias chunk 0 ----
    float4 bv0 = *(const float4*)(rprow + 0);
    float4 bv1 = *(const float4*)(rprow + 4);

    int buf = 0;
    for (int t = 0; t < NTILES; t++) {
        const int kt = t * TK;
        cp_wait0();
        __syncthreads();

        // issue prefetch of next tile into the other buffer
        if (t + 1 < NTILES) {
            const float* kn = kb + (size_t)(kt + TK) * DH;
            const float* vn = vb + (size_t)(kt + TK) * DH;
#pragma unroll
            for (int i = 0; i < 4; i++) {
                int idx = tid + i * 128;
                if (idx < TK * DH / 4) {
                    cp16(smem_u32(&Ks[buf ^ 1][0][0]) + idx * 16, kn + idx * 4);
                    cp16(smem_u32(&Vs[buf ^ 1][0][0]) + idx * 16, vn + idx * 4);
                }
            }
        }
        cp_commit();

#pragma unroll 1
        for (int c0 = 0; c0 < TK; c0 += 8) {
            // prefetch bias for next chunk (next tile's chunk 0 at tile end)
            int noff = (c0 + 8 < TK) ? (kt + c0 + 8) : (kt + TK);
            if (noff > NKV - 8) noff = 0;   // last tile: dummy (unused)
            float4 nb0 = *(const float4*)(rprow + noff);
            float4 nb1 = *(const float4*)(rprow + noff + 4);

            // ---- 8 independent score chains ----
            u64 s2[8];
            s2[0] = pack2(bv0.x, 0.f); s2[1] = pack2(bv0.y, 0.f);
            s2[2] = pack2(bv0.z, 0.f); s2[3] = pack2(bv0.w, 0.f);
            s2[4] = pack2(bv1.x, 0.f); s2[5] = pack2(bv1.y, 0.f);
            s2[6] = pack2(bv1.z, 0.f); s2[7] = pack2(bv1.w, 0.f);
#pragma unroll
            for (int i2 = 0; i2 < 8; i2++) {
#pragma unroll
                for (int j = 0; j < 8; j++) {
                    ulonglong2 kk2 = ((const ulonglong2*)Ks[buf][c0 + j])[i2];
                    s2[j] = fma2(ql2[2 * i2],     kk2.x, s2[j]);
                    s2[j] = fma2(ql2[2 * i2 + 1], kk2.y, s2[j]);
                }
            }
            float sc[8];
#pragma unroll
            for (int j = 0; j < 8; j++) {
                float a, bb2; unpack2(s2[j], a, bb2);
                sc[j] = a + bb2;
            }
            bv0 = nb0; bv1 = nb1;

            // ---- batched online softmax (max tree + conditional rescale) --
            float m01 = fmaxf(sc[0], sc[1]), m23 = fmaxf(sc[2], sc[3]);
            float m45 = fmaxf(sc[4], sc[5]), m67 = fmaxf(sc[6], sc[7]);
            float cmax = fmaxf(fmaxf(m01, m23), fmaxf(m45, m67));
            if (cmax > m) {
                float corr = __expf(m - cmax);
                l *= corr;
                u64 c2 = pack2(corr, corr);
#pragma unroll
                for (int i = 0; i < 16; i++) acc2[i] = mul2(acc2[i], c2);
                m = cmax;
            }
            float p[8];
#pragma unroll
            for (int j = 0; j < 8; j++) { p[j] = __expf(sc[j] - m); l += p[j]; }

            // ---- accumulate P @ V ----
#pragma unroll
            for (int j = 0; j < 8; j++) {
                u64 p2 = pack2(p[j], p[j]);
                const ulonglong2* vrow = (const ulonglong2*)Vs[buf][c0 + j];
#pragma unroll
                for (int i2 = 0; i2 < 8; i2++) {
                    ulonglong2 vv = vrow[i2];
                    acc2[2 * i2]     = fma2(p2, vv.x, acc2[2 * i2]);
                    acc2[2 * i2 + 1] = fma2(p2, vv.y, acc2[2 * i2 + 1]);
                }
            }
        }
        buf ^= 1;
    }

    if (valid) {
        float inv = 1.f / l;
        float* orow = out + ((size_t)(b * NQ + n)) * CC + h * DH;
#pragma unroll
        for (int i = 0; i < 8; i++) {
            float x0, x1, x2, x3;
            unpack2(acc2[2 * i], x0, x1);
            unpack2(acc2[2 * i + 1], x2, x3);
            float4 o; o.x = x0 * inv; o.y = x1 * inv; o.z = x2 * inv; o.w = x3 * inv;
            *(float4*)(orow + i * 4) = o;
        }
    }
}

// ---------------- launch ----------------
extern "C" void kernel_launch(void* const* d_in, const int* in_sizes, int n_in,
                              void* d_out, int out_size)
{
    const float* x      = (const float*)d_in[0];
    const float* relpos = (const float*)d_in[1];
    const float* Wq     = (const float*)d_in[2];
    const float* bq     = (const float*)d_in[3];
    const float* Wk     = (const float*)d_in[4];
    const float* bk     = (const float*)d_in[5];
    const float* Wv     = (const float*)d_in[6];
    const float* bv     = (const float*)d_in[7];
    const float* cw     = (const float*)d_in[8];
    const float* cb     = (const float*)d_in[9];
    const float* gamma  = (const float*)d_in[10];
    const float* beta   = (const float*)d_in[11];
    const float* mean   = (const float*)d_in[12];
    const float* var    = (const float*)d_in[13];
    const float* Wp     = (const float*)d_in[14];
    const float* bp     = (const float*)d_in[15];
    float* out = (float*)d_out;

    float *q, *k, *v, *xr, *ao;
    cudaGetSymbolAddress((void**)&q,  g_q);
    cudaGetSymbolAddress((void**)&k,  g_k);
    cudaGetSymbolAddress((void**)&v,  g_v);
    cudaGetSymbolAddress((void**)&xr, g_xr);
    cudaGetSymbolAddress((void**)&ao, g_ao);

    // 1) q projection (head-swizzled)
    proj_kernel<<<(BB * NQ) / 64, 256>>>(x, Wq, bq, q, BB * NQ, NQ, 1);
    // 2) spatial reduction conv + BN
    sr_conv_kernel<<<(BB * NKV * CC + 255) / 256, 256>>>(x, cw, cb, gamma, beta, mean, var, xr);
    // 3) fused k+v projections (head-swizzled)
    proj_kv_kernel<<<2 * (BB * NKV) / 64, 256>>>(xr, Wk, bk, k, Wv, bv, v, BB * NKV, NKV);
    // 4) fused attention with online softmax
    dim3 ag((NQ + TQ - 1) / TQ, HEADS, BB);
    attn_kernel<<<ag, 128>>>(q, k, v, relpos, ao);
    // 5) output projection
    proj_kernel<<<(BB * NQ) / 64, 256>>>(ao, Wp, bp, out, BB * NQ, NQ, 0);
}

// round 4
// speedup vs baseline: 2.4732x; 1.3205x over previous
#include <cuda_runtime.h>
#include <cstdint>

// ---------------- problem constants ----------------
#define BB      8
#define HEADS   4
#define NQ      3136
#define NKV     784
#define DH      32      // head dim
#define CC      128
#define TQ2     256     // queries per CTA (attention): 2 per thread
#define TK      112     // kv tile (784 = 7*112)
#define NTILES  (NKV / TK)

typedef unsigned long long u64;

// ---------------- scratch (device globals; no allocation) ----------------
__device__ float g_q [BB * HEADS * NQ  * DH];   // (B,H,N,32)
__device__ float g_k [BB * HEADS * NKV * DH];   // (B,H,Nkv,32)
__device__ float g_v [BB * HEADS * NKV * DH];
__device__ float g_xr[BB * NKV * CC];           // spatially reduced tokens
__device__ float g_ao[BB * NQ  * CC];           // attention output (B,N,C)

// ---------------- f32x2 packed helpers (Blackwell FFMA2) ----------------
__device__ __forceinline__ u64 pack2(float x, float y) {
    u64 r; asm("mov.b64 %0, {%1, %2};" : "=l"(r) : "f"(x), "f"(y)); return r;
}
__device__ __forceinline__ void unpack2(u64 v, float& x, float& y) {
    asm("mov.b64 {%0, %1}, %2;" : "=f"(x), "=f"(y) : "l"(v));
}
__device__ __forceinline__ u64 fma2(u64 a, u64 b, u64 c) {
    u64 d; asm("fma.rn.f32x2 %0, %1, %2, %3;" : "=l"(d) : "l"(a), "l"(b), "l"(c)); return d;
}
__device__ __forceinline__ u64 mul2(u64 a, u64 b) {
    u64 d; asm("mul.rn.f32x2 %0, %1, %2;" : "=l"(d) : "l"(a), "l"(b)); return d;
}

// ---------------- cp.async helpers ----------------
__device__ __forceinline__ unsigned smem_u32(const void* p) {
    return (unsigned)__cvta_generic_to_shared(p);
}
__device__ __forceinline__ void cp16(unsigned dst, const void* src) {
    asm volatile("cp.async.cg.shared.global [%0], [%1], 16;\n" :: "r"(dst), "l"(src));
}
__device__ __forceinline__ void cp_commit() {
    asm volatile("cp.async.commit_group;\n" ::: "memory");
}
__device__ __forceinline__ void cp_wait0() {
    asm volatile("cp.async.wait_group 0;\n" ::: "memory");
}

// ---------------- projection GEMM body: Y = X(Mx128) @ W(128x128) + b ------
__device__ __forceinline__ void proj_body(
    const float* __restrict__ X, const float* __restrict__ W,
    const float* __restrict__ bias, float* __restrict__ Y,
    int rowb, int M, int RPB, int swizzle)
{
    __shared__ __align__(16) float Xs[32][66];    // [k][row], pad 2
    __shared__ __align__(16) float Ws[32][128];

    const int tid   = threadIdx.x;
    const int col_t = tid & 31;   // 0..31 -> 4 cols each
    const int row_t = tid >> 5;   // 0..7  -> 8 rows each

    u64 acc2[4][4];               // [rowpair][col]
#pragma unroll
    for (int rp = 0; rp < 4; rp++)
#pragma unroll
        for (int c = 0; c < 4; c++) acc2[rp][c] = 0ULL;

    for (int kc = 0; kc < 128; kc += 32) {
        __syncthreads();
#pragma unroll
        for (int i = 0; i < 8; i++) {          // X tile: 64 rows x 32 k
            int idx = tid + i * 256;
            int r = idx >> 5, kk = idx & 31;
            Xs[kk][r] = X[(size_t)(rowb + r) * CC + kc + kk];
        }
#pragma unroll
        for (int i = 0; i < 16; i++) {         // W tile: 32 k x 128 cols
            int idx = tid + i * 256;
            int kk = idx >> 7, cc2 = idx & 127;
            Ws[kk][cc2] = W[(size_t)(kc + kk) * CC + cc2];
        }
        __syncthreads();
#pragma unroll
        for (int kk = 0; kk < 32; kk++) {
            float4 wv = *(const float4*)&Ws[kk][col_t * 4];
            u64 wd0 = pack2(wv.x, wv.x);
            u64 wd1 = pack2(wv.y, wv.y);
            u64 wd2 = pack2(wv.z, wv.z);
            u64 wd3 = pack2(wv.w, wv.w);
            const u64* xrow = (const u64*)&Xs[kk][row_t * 8];
#pragma unroll
            for (int rp = 0; rp < 4; rp++) {
                u64 xp = xrow[rp];
                acc2[rp][0] = fma2(xp, wd0, acc2[rp][0]);
                acc2[rp][1] = fma2(xp, wd1, acc2[rp][1]);
                acc2[rp][2] = fma2(xp, wd2, acc2[rp][2]);
                acc2[rp][3] = fma2(xp, wd3, acc2[rp][3]);
            }
        }
    }

    const int col0 = col_t * 4;
    float4 bv = *(const float4*)&bias[col0];
#pragma unroll
    for (int rp = 0; rp < 4; rp++) {
        float lo[4], hi[4];
#pragma unroll
        for (int c = 0; c < 4; c++) unpack2(acc2[rp][c], lo[c], hi[c]);
        int row0 = rowb + row_t * 8 + 2 * rp;
#pragma unroll
        for (int half = 0; half < 2; half++) {
            int row = row0 + half;
            if (row >= M) continue;
            float* s = half ? hi : lo;
            float4 o;
            o.x = s[0] + bv.x; o.y = s[1] + bv.y;
            o.z = s[2] + bv.z; o.w = s[3] + bv.w;
            if (swizzle) {
                int b = row / RPB, n = row % RPB;
                int h = col0 >> 5, d = col0 & 31;
                *(float4*)&Y[(((size_t)(b * HEADS + h) * RPB + n)) * DH + d] = o;
            } else {
                *(float4*)&Y[(size_t)row * CC + col0] = o;
            }
        }
    }
}

__global__ __launch_bounds__(256) void proj_kernel(
    const float* __restrict__ X, const float* __restrict__ W,
    const float* __restrict__ bias, float* __restrict__ Y,
    int M, int RPB, int swizzle)
{
    proj_body(X, W, bias, Y, blockIdx.x * 64, M, RPB, swizzle);
}

__global__ __launch_bounds__(256) void proj_kv_kernel(
    const float* __restrict__ X,
    const float* __restrict__ Wk, const float* __restrict__ bk, float* __restrict__ K,
    const float* __restrict__ Wv, const float* __restrict__ bv, float* __restrict__ V,
    int M, int RPB)
{
    int nb = gridDim.x >> 1;
    int half = blockIdx.x >= nb;
    int rowb = (blockIdx.x - (half ? nb : 0)) * 64;
    if (half) proj_body(X, Wv, bv, V, rowb, M, RPB, 1);
    else      proj_body(X, Wk, bk, K, rowb, M, RPB, 1);
}

// ---------------- spatial reduction: depthwise 2x2 stride-2 conv + BN ------
__global__ void sr_conv_kernel(
    const float* __restrict__ x, const float* __restrict__ cw, const float* __restrict__ cb,
    const float* __restrict__ gamma, const float* __restrict__ beta,
    const float* __restrict__ mean, const float* __restrict__ var,
    float* __restrict__ xr)
{
    int t = blockIdx.x * blockDim.x + threadIdx.x;
    if (t >= BB * NKV * CC) return;
    int c = t & (CC - 1);
    int p = (t >> 7) % NKV;
    int b = t / (NKV * CC);
    int oy = p / 28, ox = p % 28;

    const float* xb = x + (size_t)b * NQ * CC;
    float s = 0.f;
#pragma unroll
    for (int i = 0; i < 2; i++)
#pragma unroll
        for (int j = 0; j < 2; j++)
            s += xb[(size_t)((2 * oy + i) * 56 + (2 * ox + j)) * CC + c] * cw[c * 4 + i * 2 + j];
    s += cb[c];
    float iv = gamma[c] * rsqrtf(var[c] + 1e-5f);
    xr[t] = s * iv + (beta[c] - mean[c] * iv);
}

// ---------------- fused flash attention v4 --------------------------------
// 2 queries/thread (q and q+128), 256 q/CTA: every K/V LDS.128 feeds both
// queries (halves L1 wavefronts per query). K/V double-buffered cp.async,
// TK=112 (7 tiles). Bias loaded direct from gmem at chunk top; latency hidden
// by the score FFMA2 block.
__global__ __launch_bounds__(128, 2) void attn_kernel(
    const float* __restrict__ q, const float* __restrict__ k, const float* __restrict__ v,
    const float* __restrict__ relpos, float* __restrict__ out)
{
    __shared__ __align__(16) float Ks[2][TK][DH];
    __shared__ __align__(16) float Vs[2][TK][DH];

    const int b  = blockIdx.z;
    const int h  = blockIdx.y;
    const int qt = blockIdx.x;
    const int tid = threadIdx.x;
    const int nA = qt * TQ2 + tid;
    const int nB = nA + 128;
    const bool vA = (nA < NQ), vB = (nB < NQ);
    const int ncA = vA ? nA : (NQ - 1);
    const int ncB = vB ? nB : (NQ - 1);
    const float scale = 0.17677669529663687f;  // 32^-0.5

    const float* kb = k + (size_t)(b * HEADS + h) * NKV * DH;
    const float* vb = v + (size_t)(b * HEADS + h) * NKV * DH;
    const float* rpA = relpos + (size_t)h * NQ * NKV + (size_t)ncA * NKV;
    const float* rpB = relpos + (size_t)h * NQ * NKV + (size_t)ncB * NKV;

    // load q rows (pre-scaled), packed as f32x2
    u64 qlA[16], qlB[16];
    {
        const float* qa = q + ((size_t)(b * HEADS + h) * NQ + ncA) * DH;
        const float* qb2 = q + ((size_t)(b * HEADS + h) * NQ + ncB) * DH;
#pragma unroll
        for (int i = 0; i < 8; i++) {
            float4 t4 = *(const float4*)(qa + i * 4);
            qlA[2 * i]     = pack2(t4.x * scale, t4.y * scale);
            qlA[2 * i + 1] = pack2(t4.z * scale, t4.w * scale);
            float4 t5 = *(const float4*)(qb2 + i * 4);
            qlB[2 * i]     = pack2(t5.x * scale, t5.y * scale);
            qlB[2 * i + 1] = pack2(t5.z * scale, t5.w * scale);
        }
    }

    float mA = -1e30f, lA = 0.f, mB = -1e30f, lB = 0.f;
    u64 accA[16], accB[16];
#pragma unroll
    for (int i = 0; i < 16; i++) { accA[i] = 0ULL; accB[i] = 0ULL; }

    // ---- prefetch tile 0: 112*32/4 = 896 vec4 per array, 7 per thread ----
#pragma unroll
    for (int i = 0; i < 7; i++) {
        int idx = tid + i * 128;
        cp16(smem_u32(&Ks[0][0][0]) + idx * 16, kb + idx * 4);
        cp16(smem_u32(&Vs[0][0][0]) + idx * 16, vb + idx * 4);
    }
    cp_commit();

    int buf = 0;
    for (int t = 0; t < NTILES; t++) {
        const int kt = t * TK;
        cp_wait0();
        __syncthreads();

        if (t + 1 < NTILES) {
            const float* kn = kb + (size_t)(kt + TK) * DH;
            const float* vn = vb + (size_t)(kt + TK) * DH;
#pragma unroll
            for (int i = 0; i < 7; i++) {
                int idx = tid + i * 128;
                cp16(smem_u32(&Ks[buf ^ 1][0][0]) + idx * 16, kn + idx * 4);
                cp16(smem_u32(&Vs[buf ^ 1][0][0]) + idx * 16, vn + idx * 4);
            }
        }
        cp_commit();

#pragma unroll 1
        for (int c0 = 0; c0 < TK; c0 += 8) {
            // bias for this chunk (issued early; consumed after score loop)
            float4 ba0 = *(const float4*)(rpA + kt + c0);
            float4 ba1 = *(const float4*)(rpA + kt + c0 + 4);
            float4 bb0 = *(const float4*)(rpB + kt + c0);
            float4 bb1 = *(const float4*)(rpB + kt + c0 + 4);

            // ---- score chains: 8 kv x 2 queries, K row LDS shared ----
            u64 s2a[8], s2b[8];
#pragma unroll
            for (int j = 0; j < 8; j++) { s2a[j] = 0ULL; s2b[j] = 0ULL; }
#pragma unroll
            for (int i2 = 0; i2 < 8; i2++) {
#pragma unroll
                for (int j = 0; j < 8; j++) {
                    ulonglong2 kk2 = ((const ulonglong2*)Ks[buf][c0 + j])[i2];
                    s2a[j] = fma2(qlA[2 * i2],     kk2.x, s2a[j]);
                    s2a[j] = fma2(qlA[2 * i2 + 1], kk2.y, s2a[j]);
                    s2b[j] = fma2(qlB[2 * i2],     kk2.x, s2b[j]);
                    s2b[j] = fma2(qlB[2 * i2 + 1], kk2.y, s2b[j]);
                }
            }
            float scA[8], scB[8];
            {
                const float* bap = (const float*)&ba0;  // ba0..ba1 contiguous? keep explicit
                float bAv[8] = {ba0.x, ba0.y, ba0.z, ba0.w, ba1.x, ba1.y, ba1.z, ba1.w};
                float bBv[8] = {bb0.x, bb0.y, bb0.z, bb0.w, bb1.x, bb1.y, bb1.z, bb1.w};
                (void)bap;
#pragma unroll
                for (int j = 0; j < 8; j++) {
                    float x0, x1; unpack2(s2a[j], x0, x1);
                    scA[j] = x0 + x1 + bAv[j];
                    float y0, y1; unpack2(s2b[j], y0, y1);
                    scB[j] = y0 + y1 + bBv[j];
                }
            }

            // ---- batched online softmax, query A ----
            {
                float m01 = fmaxf(scA[0], scA[1]), m23 = fmaxf(scA[2], scA[3]);
                float m45 = fmaxf(scA[4], scA[5]), m67 = fmaxf(scA[6], scA[7]);
                float cmax = fmaxf(fmaxf(m01, m23), fmaxf(m45, m67));
                if (cmax > mA) {
                    float corr = __expf(mA - cmax);
                    lA *= corr;
                    u64 c2 = pack2(corr, corr);
#pragma unroll
                    for (int i = 0; i < 16; i++) accA[i] = mul2(accA[i], c2);
                    mA = cmax;
                }
            }
            float pA[8];
#pragma unroll
            for (int j = 0; j < 8; j++) { pA[j] = __expf(scA[j] - mA); lA += pA[j]; }

            // ---- batched online softmax, query B ----
            {
                float m01 = fmaxf(scB[0], scB[1]), m23 = fmaxf(scB[2], scB[3]);
                float m45 = fmaxf(scB[4], scB[5]), m67 = fmaxf(scB[6], scB[7]);
                float cmax = fmaxf(fmaxf(m01, m23), fmaxf(m45, m67));
                if (cmax > mB) {
                    float corr = __expf(mB - cmax);
                    lB *= corr;
                    u64 c2 = pack2(corr, corr);
#pragma unroll
                    for (int i = 0; i < 16; i++) accB[i] = mul2(accB[i], c2);
                    mB = cmax;
                }
            }
            float pB[8];
#pragma unroll
            for (int j = 0; j < 8; j++) { pB[j] = __expf(scB[j] - mB); lB += pB[j]; }

            // ---- accumulate P @ V (V row LDS shared by both queries) ----
#pragma unroll
            for (int j = 0; j < 8; j++) {
                u64 p2a = pack2(pA[j], pA[j]);
                u64 p2b = pack2(pB[j], pB[j]);
                const ulonglong2* vrow = (const ulonglong2*)Vs[buf][c0 + j];
#pragma unroll
                for (int i2 = 0; i2 < 8; i2++) {
                    ulonglong2 vv = vrow[i2];
                    accA[2 * i2]     = fma2(p2a, vv.x, accA[2 * i2]);
                    accA[2 * i2 + 1] = fma2(p2a, vv.y, accA[2 * i2 + 1]);
                    accB[2 * i2]     = fma2(p2b, vv.x, accB[2 * i2]);
                    accB[2 * i2 + 1] = fma2(p2b, vv.y, accB[2 * i2 + 1]);
                }
            }
        }
        buf ^= 1;
    }

    if (vA) {
        float inv = 1.f / lA;
        float* orow = out + ((size_t)(b * NQ + nA)) * CC + h * DH;
#pragma unroll
        for (int i = 0; i < 8; i++) {
            float x0, x1, x2, x3;
            unpack2(accA[2 * i], x0, x1);
            unpack2(accA[2 * i + 1], x2, x3);
            float4 o; o.x = x0 * inv; o.y = x1 * inv; o.z = x2 * inv; o.w = x3 * inv;
            *(float4*)(orow + i * 4) = o;
        }
    }
    if (vB) {
        float inv = 1.f / lB;
        float* orow = out + ((size_t)(b * NQ + nB)) * CC + h * DH;
#pragma unroll
        for (int i = 0; i < 8; i++) {
            float x0, x1, x2, x3;
            unpack2(accB[2 * i], x0, x1);
            unpack2(accB[2 * i + 1], x2, x3);
            float4 o; o.x = x0 * inv; o.y = x1 * inv; o.z = x2 * inv; o.w = x3 * inv;
            *(float4*)(orow + i * 4) = o;
        }
    }
}

// ---------------- launch ----------------
extern "C" void kernel_launch(void* const* d_in, const int* in_sizes, int n_in,
                              void* d_out, int out_size)
{
    const float* x      = (const float*)d_in[0];
    const float* relpos = (const float*)d_in[1];
    const float* Wq     = (const float*)d_in[2];
    const float* bq     = (const float*)d_in[3];
    const float* Wk     = (const float*)d_in[4];
    const float* bk     = (const float*)d_in[5];
    const float* Wv     = (const float*)d_in[6];
    const float* bv     = (const float*)d_in[7];
    const float* cw     = (const float*)d_in[8];
    const float* cb     = (const float*)d_in[9];
    const float* gamma  = (const float*)d_in[10];
    const float* beta   = (const float*)d_in[11];
    const float* mean   = (const float*)d_in[12];
    const float* var    = (const float*)d_in[13];
    const float* Wp     = (const float*)d_in[14];
    const float* bp     = (const float*)d_in[15];
    float* out = (float*)d_out;

    float *q, *k, *v, *xr, *ao;
    cudaGetSymbolAddress((void**)&q,  g_q);
    cudaGetSymbolAddress((void**)&k,  g_k);
    cudaGetSymbolAddress((void**)&v,  g_v);
    cudaGetSymbolAddress((void**)&xr, g_xr);
    cudaGetSymbolAddress((void**)&ao, g_ao);

    // 1) q projection (head-swizzled)
    proj_kernel<<<(BB * NQ) / 64, 256>>>(x, Wq, bq, q, BB * NQ, NQ, 1);
    // 2) spatial reduction conv + BN
    sr_conv_kernel<<<(BB * NKV * CC + 255) / 256, 256>>>(x, cw, cb, gamma, beta, mean, var, xr);
    // 3) fused k+v projections (head-swizzled)
    proj_kv_kernel<<<2 * (BB * NKV) / 64, 256>>>(xr, Wk, bk, k, Wv, bv, v, BB * NKV, NKV);
    // 4) fused attention with online softmax (2 queries/thread)
    dim3 ag((NQ + TQ2 - 1) / TQ2, HEADS, BB);
    attn_kernel<<<ag, 128>>>(q, k, v, relpos, ao);
    // 5) output projection
    proj_kernel<<<(BB * NQ) / 64, 256>>>(ao, Wp, bp, out, BB * NQ, NQ, 0);
}

// round 6
// speedup vs baseline: 3.8932x; 1.5742x over previous
#include <cuda_runtime.h>
#include <cstdint>

// ---------------- problem constants ----------------
#define BB      8
#define HEADS   4
#define NQ      3136
#define NKV     784
#define DH      32
#define CC      128
#define TN      64                 // kv tile (12 full tiles + tail of 16)
#define NFULL   12
#define VSTRIDE 26624              // 13 tiles * 2048 floats per (b,h)

typedef unsigned long long u64;

// ---------------- scratch (device globals; no allocation) ----------------
__device__ float g_q [BB * HEADS * NQ  * DH];      // permuted d', tf32, pre-scaled
__device__ float g_k [BB * HEADS * NKV * DH];      // permuted d', tf32
__device__ float g_v [BB * HEADS * VSTRIDE];       // tile-permuted Vp, tf32
__device__ float g_xr[BB * NKV * CC];
__device__ float g_ao[BB * NQ  * CC];

// ---------------- helpers ----------------
__device__ __forceinline__ u64 pack2(float x, float y) {
    u64 r; asm("mov.b64 %0, {%1, %2};" : "=l"(r) : "f"(x), "f"(y)); return r;
}
__device__ __forceinline__ void unpack2(u64 v, float& x, float& y) {
    asm("mov.b64 {%0, %1}, %2;" : "=f"(x), "=f"(y) : "l"(v));
}
__device__ __forceinline__ u64 fma2(u64 a, u64 b, u64 c) {
    u64 d; asm("fma.rn.f32x2 %0, %1, %2, %3;" : "=l"(d) : "l"(a), "l"(b), "l"(c)); return d;
}
__device__ __forceinline__ float to_tf32(float x) {
    float r; asm("cvt.rna.tf32.f32 %0, %1;" : "=f"(r) : "f"(x)); return r;
}
__device__ __forceinline__ unsigned smem_u32(const void* p) {
    return (unsigned)__cvta_generic_to_shared(p);
}
__device__ __forceinline__ void cp16(unsigned dst, const void* src) {
    asm volatile("cp.async.cg.shared.global [%0], [%1], 16;\n" :: "r"(dst), "l"(src));
}
__device__ __forceinline__ void cp_commit() {
    asm volatile("cp.async.commit_group;\n" ::: "memory");
}
__device__ __forceinline__ void cp_wait0() {
    asm volatile("cp.async.wait_group 0;\n" ::: "memory");
}

// mma.sync m16n8k8 tf32 (base PTX, sm_80+; drives tensor pipe on sm_103)
__device__ __forceinline__ void mma8(float c[4], float a0, float a1, float a2, float a3,
                                     float b0, float b1) {
    asm volatile(
        "mma.sync.aligned.m16n8k8.row.col.f32.tf32.tf32.f32 "
        "{%0,%1,%2,%3}, {%4,%5,%6,%7}, {%8,%9}, {%0,%1,%2,%3};"
        : "+f"(c[0]), "+f"(c[1]), "+f"(c[2]), "+f"(c[3])
        : "r"(__float_as_uint(a0)), "r"(__float_as_uint(a1)),
          "r"(__float_as_uint(a2)), "r"(__float_as_uint(a3)),
          "r"(__float_as_uint(b0)), "r"(__float_as_uint(b1)));
}

// ---------------- projection GEMM: Y = X(Mx128) @ W(128x128) + b ------
// mode 0: plain row-major.  mode 1: K (head-split, d-permute, tf32)
// mode 2: Q (head-split, d-permute, tf32, pre-scaled)
// mode 4: V (head-split, kv-tile permute Vp[r%4][d][r/4], tf32)
__device__ __forceinline__ void proj_body(
    const float* __restrict__ X, const float* __restrict__ W,
    const float* __restrict__ bias, float* __restrict__ Y,
    int rowb, int M, int RPB, int mode)
{
    __shared__ __align__(16) float Xs[32][66];
    __shared__ __align__(16) float Ws[32][128];

    const int tid   = threadIdx.x;
    const int col_t = tid & 31;
    const int row_t = tid >> 5;

    u64 acc2[4][4];
#pragma unroll
    for (int rp = 0; rp < 4; rp++)
#pragma unroll
        for (int c = 0; c < 4; c++) acc2[rp][c] = 0ULL;

    for (int kc = 0; kc < 128; kc += 32) {
        __syncthreads();
#pragma unroll
        for (int i = 0; i < 8; i++) {
            int idx = tid + i * 256;
            int r = idx >> 5, kk = idx & 31;
            Xs[kk][r] = X[(size_t)(rowb + r) * CC + kc + kk];
        }
#pragma unroll
        for (int i = 0; i < 16; i++) {
            int idx = tid + i * 256;
            int kk = idx >> 7, cc2 = idx & 127;
            Ws[kk][cc2] = W[(size_t)(kc + kk) * CC + cc2];
        }
        __syncthreads();
#pragma unroll
        for (int kk = 0; kk < 32; kk++) {
            float4 wv = *(const float4*)&Ws[kk][col_t * 4];
            u64 wd0 = pack2(wv.x, wv.x);
            u64 wd1 = pack2(wv.y, wv.y);
            u64 wd2 = pack2(wv.z, wv.z);
            u64 wd3 = pack2(wv.w, wv.w);
            const u64* xrow = (const u64*)&Xs[kk][row_t * 8];
#pragma unroll
            for (int rp = 0; rp < 4; rp++) {
                u64 xp = xrow[rp];
                acc2[rp][0] = fma2(xp, wd0, acc2[rp][0]);
                acc2[rp][1] = fma2(xp, wd1, acc2[rp][1]);
                acc2[rp][2] = fma2(xp, wd2, acc2[rp][2]);
                acc2[rp][3] = fma2(xp, wd3, acc2[rp][3]);
            }
        }
    }

    const float scale = 0.17677669529663687f;  // 32^-0.5
    const int col0 = col_t * 4;
    float4 bv = *(const float4*)&bias[col0];
#pragma unroll
    for (int rp = 0; rp < 4; rp++) {
        float lo[4], hi[4];
#pragma unroll
        for (int c = 0; c < 4; c++) unpack2(acc2[rp][c], lo[c], hi[c]);
        int row0 = rowb + row_t * 8 + 2 * rp;
#pragma unroll
        for (int half = 0; half < 2; half++) {
            int row = row0 + half;
            if (row >= M) continue;
            float* s = half ? hi : lo;
            float o[4];
            o[0] = s[0] + bv.x; o[1] = s[1] + bv.y;
            o[2] = s[2] + bv.z; o[3] = s[3] + bv.w;
            if (mode == 0) {
                *(float4*)&Y[(size_t)row * CC + col0] = make_float4(o[0], o[1], o[2], o[3]);
            } else {
                int b = row / RPB, n = row % RPB;
                int h = col0 >> 5, dbase = col0 & 31;
                if (mode == 4) {
                    int tile = n >> 6, rr = n & 63;
                    float* bp = &Y[(size_t)(b * HEADS + h) * VSTRIDE
                                   + tile * 2048 + (rr & 3) * 512 + (rr >> 2)];
#pragma unroll
                    for (int i = 0; i < 4; i++)
                        bp[(dbase + i) * 16] = to_tf32(o[i]);
                } else {
                    float* bp = &Y[((size_t)(b * HEADS + h) * RPB + n) * DH];
#pragma unroll
                    for (int i = 0; i < 4; i++) {
                        int d = dbase + i;
                        int dp = (d & 3) * 8 + (d >> 2);
                        float val = (mode == 2) ? o[i] * scale : o[i];
                        bp[dp] = to_tf32(val);
                    }
                }
            }
        }
    }
}

__global__ __launch_bounds__(256) void proj_kernel(
    const float* __restrict__ X, const float* __restrict__ W,
    const float* __restrict__ bias, float* __restrict__ Y,
    int M, int RPB, int mode)
{
    proj_body(X, W, bias, Y, blockIdx.x * 64, M, RPB, mode);
}

__global__ __launch_bounds__(256) void proj_kv_kernel(
    const float* __restrict__ X,
    const float* __restrict__ Wk, const float* __restrict__ bk, float* __restrict__ K,
    const float* __restrict__ Wv, const float* __restrict__ bv, float* __restrict__ V,
    int M, int RPB)
{
    int nb = gridDim.x >> 1;
    int half = blockIdx.x >= nb;
    int rowb = (blockIdx.x - (half ? nb : 0)) * 64;
    if (half) proj_body(X, Wv, bv, V, rowb, M, RPB, 4);
    else      proj_body(X, Wk, bk, K, rowb, M, RPB, 1);
}

// ---------------- spatial reduction conv + BN ------
__global__ void sr_conv_kernel(
    const float* __restrict__ x, const float* __restrict__ cw, const float* __restrict__ cb,
    const float* __restrict__ gamma, const float* __restrict__ beta,
    const float* __restrict__ mean, const float* __restrict__ var,
    float* __restrict__ xr)
{
    int t = blockIdx.x * blockDim.x + threadIdx.x;
    if (t >= BB * NKV * CC) return;
    int c = t & (CC - 1);
    int p = (t >> 7) % NKV;
    int b = t / (NKV * CC);
    int oy = p / 28, ox = p % 28;

    const float* xb = x + (size_t)b * NQ * CC;
    float s = 0.f;
#pragma unroll
    for (int i = 0; i < 2; i++)
#pragma unroll
        for (int j = 0; j < 2; j++)
            s += xb[(size_t)((2 * oy + i) * 56 + (2 * ox + j)) * CC + c] * cw[c * 4 + i * 2 + j];
    s += cb[c];
    float iv = gamma[c] * rsqrtf(var[c] + 1e-5f);
    xr[t] = s * iv + (beta[c] - mean[c] * iv);
}

// ---------------- mma attention ----------------
// smem float offsets
#define KS_F    0          // 2 x (64 x 36)      = 4608 floats
#define VS_F    4608       // 2 x (4 x 516)      = 4128 floats
#define PS_F    8736       // 4 warps x (32 x 68)= 8704 floats
#define SMEM_F  17440      // 69760 bytes

// per-tile body. NF = kv/8 (8 for full 64-kv tiles, 2 for 16-kv tail)
template<int NF>
__device__ __forceinline__ void tile_body(
    const float* __restrict__ Ksm, const float* __restrict__ Vsm, float* __restrict__ Pw,
    const float (&qreg)[4][8], float (&o)[2][4][4], float (&sums)[4],
    const float* const (&rpr)[4], int ktile, int g, int t)
{
    // ---- S = Q @ K^T (tensor), then exp(S+bias) -> P (smem) ----
#pragma unroll
    for (int nf = 0; nf < NF; nf++) {
        const float* kp = Ksm + (8 * nf + g) * 36 + t * 8;
        float4 k0 = *(const float4*)kp;
        float4 k1 = *(const float4*)(kp + 4);
        float kb[8] = {k0.x, k0.y, k0.z, k0.w, k1.x, k1.y, k1.z, k1.w};
        float c0[4] = {0.f, 0.f, 0.f, 0.f};
        float c1[4] = {0.f, 0.f, 0.f, 0.f};
#pragma unroll
        for (int s = 0; s < 4; s++) {
            mma8(c0, qreg[0][2*s], qreg[1][2*s], qreg[0][2*s+1], qreg[1][2*s+1],
                 kb[2*s], kb[2*s+1]);
            mma8(c1, qreg[2][2*s], qreg[3][2*s], qreg[2][2*s+1], qreg[3][2*s+1],
                 kb[2*s], kb[2*s+1]);
        }
        int off = ktile + 8 * nf + 2 * t;
        float2 b0 = *(const float2*)(rpr[0] + off);
        float2 b1 = *(const float2*)(rpr[1] + off);
        float2 b2 = *(const float2*)(rpr[2] + off);
        float2 b3 = *(const float2*)(rpr[3] + off);
        float p00 = to_tf32(__expf(c0[0] + b0.x)), p01 = to_tf32(__expf(c0[1] + b0.y));
        float p10 = to_tf32(__expf(c0[2] + b1.x)), p11 = to_tf32(__expf(c0[3] + b1.y));
        float p20 = to_tf32(__expf(c1[0] + b2.x)), p21 = to_tf32(__expf(c1[1] + b2.y));
        float p30 = to_tf32(__expf(c1[2] + b3.x)), p31 = to_tf32(__expf(c1[3] + b3.y));
        sums[0] += p00 + p01; sums[1] += p10 + p11;
        sums[2] += p20 + p21; sums[3] += p30 + p31;
        int pc = 8 * nf + 2 * t;
        *(float2*)(Pw + (g     ) * 68 + pc) = make_float2(p00, p01);
        *(float2*)(Pw + (g +  8) * 68 + pc) = make_float2(p10, p11);
        *(float2*)(Pw + (g + 16) * 68 + pc) = make_float2(p20, p21);
        *(float2*)(Pw + (g + 24) * 68 + pc) = make_float2(p30, p31);
    }
    __syncwarp();

    // ---- O += P @ V (tensor) ----
#pragma unroll
    for (int s = 0; s < NF; s++) {
        float a00 = Pw[(g     ) * 68 + 8*s + t];
        float a01 = Pw[(g +  8) * 68 + 8*s + t];
        float a02 = Pw[(g     ) * 68 + 8*s + t + 4];
        float a03 = Pw[(g +  8) * 68 + 8*s + t + 4];
        float a10 = Pw[(g + 16) * 68 + 8*s + t];
        float a11 = Pw[(g + 24) * 68 + 8*s + t];
        float a12 = Pw[(g + 16) * 68 + 8*s + t + 4];
        float a13 = Pw[(g + 24) * 68 + 8*s + t + 4];
#pragma unroll
        for (int nf = 0; nf < 4; nf++) {
            float2 bv = *(const float2*)(Vsm + t * 516 + (8 * nf + g) * 16 + 2 * s);
            mma8(o[0][nf], a00, a01, a02, a03, bv.x, bv.y);
            mma8(o[1][nf], a10, a11, a12, a13, bv.x, bv.y);
        }
    }
    __syncwarp();
}

__global__ __launch_bounds__(128, 3) void attn_mma_kernel(
    const float* __restrict__ q, const float* __restrict__ k, const float* __restrict__ v,
    const float* __restrict__ relpos, float* __restrict__ out)
{
    extern __shared__ __align__(16) float dsm[];

    const int b   = blockIdx.z;
    const int h   = blockIdx.y;
    const int qt  = blockIdx.x;
    const int tid = threadIdx.x;
    const int lane = tid & 31, w = tid >> 5;
    const int g = lane >> 2, t = lane & 3;
    const int q0 = qt * 128;

    const float* qb = q + (size_t)(b * HEADS + h) * NQ * DH;
    const float* kb = k + (size_t)(b * HEADS + h) * NKV * DH;
    const float* vb = v + (size_t)(b * HEADS + h) * VSTRIDE;

    float* Pw = dsm + PS_F + w * 2176;

    // ---- Q fragments (persistent) + bias row pointers ----
    float qreg[4][8];
    int qraw[4];
    const float* rpr[4];
#pragma unroll
    for (int rr = 0; rr < 4; rr++) {
        int qg = q0 + 32 * w + g + 8 * rr;
        qraw[rr] = qg;
        if (qg >= NQ) qg = NQ - 1;
        const float* qp = qb + (size_t)qg * DH + t * 8;
        float4 x0 = *(const float4*)qp;
        float4 x1 = *(const float4*)(qp + 4);
        qreg[rr][0] = x0.x; qreg[rr][1] = x0.y; qreg[rr][2] = x0.z; qreg[rr][3] = x0.w;
        qreg[rr][4] = x1.x; qreg[rr][5] = x1.y; qreg[rr][6] = x1.z; qreg[rr][7] = x1.w;
        rpr[rr] = relpos + ((size_t)h * NQ + qg) * NKV;
    }

    float o[2][4][4];
#pragma unroll
    for (int i = 0; i < 2; i++)
#pragma unroll
        for (int j = 0; j < 4; j++)
#pragma unroll
            for (int c = 0; c < 4; c++) o[i][j][c] = 0.f;
    float sums[4] = {0.f, 0.f, 0.f, 0.f};

    const unsigned kd_base = smem_u32(dsm);                 // bytes
    const unsigned vd_base = smem_u32(dsm + VS_F);

    // prefetch tile 0 (full: 512 K-chunks + 512 V-chunks of 16B)
    {
        const float* kg = kb;
        const float* vg = vb;
#pragma unroll
        for (int i = 0; i < 8; i++) {
            int idx = tid + i * 128;
            if (idx < 512) {
                int r = idx >> 3, c = idx & 7;
                cp16(kd_base + r * 144 + c * 16, kg + idx * 4);
            } else {
                int j = idx - 512;
                int grp = j >> 7, oo = j & 127;
                cp16(vd_base + grp * 2064 + oo * 16, vg + j * 4);
            }
        }
    }
    cp_commit();

    for (int tt = 0; tt < 13; tt++) {
        const int buf = tt & 1;
        cp_wait0();
        __syncthreads();

        if (tt + 1 < 13) {
            const int nb = (buf ^ 1);
            const unsigned kd = kd_base + nb * 9216;
            const unsigned vd = vd_base + nb * 8256;
            const float* kg = kb + (size_t)(tt + 1) * 2048;
            const float* vg = vb + (size_t)(tt + 1) * 2048;
            if (tt + 1 < NFULL) {
#pragma unroll
                for (int i = 0; i < 8; i++) {
                    int idx = tid + i * 128;
                    if (idx < 512) {
                        int r = idx >> 3, c = idx & 7;
                        cp16(kd + r * 144 + c * 16, kg + idx * 4);
                    } else {
                        int j = idx - 512;
                        int grp = j >> 7, oo = j & 127;
                        cp16(vd + grp * 2064 + oo * 16, vg + j * 4);
                    }
                }
            } else {
                // tail: 16 kv rows -> 128 K-chunks + 128 V-chunks
#pragma unroll
                for (int i = 0; i < 2; i++) {
                    int idx = tid + i * 128;
                    if (idx < 128) {
                        int r = idx >> 3, c = idx & 7;
                        cp16(kd + r * 144 + c * 16, kg + idx * 4);
                    } else {
                        int j = idx - 128;
                        int grp = j >> 5, d = j & 31;
                        cp16(vd + grp * 2064 + d * 64, vg + grp * 512 + d * 16);
                    }
                }
            }
        }
        cp_commit();

        const float* Ksm = dsm + buf * 2304;
        const float* Vsm = dsm + VS_F + buf * 2064;
        if (tt < NFULL)
            tile_body<8>(Ksm, Vsm, Pw, qreg, o, sums, rpr, tt * TN, g, t);
        else
            tile_body<2>(Ksm, Vsm, Pw, qreg, o, sums, rpr, tt * TN, g, t);
    }

    // ---- finalize: quad-reduce row sums, normalize, write ----
    float inv[4];
#pragma unroll
    for (int rr = 0; rr < 4; rr++) {
        float s = sums[rr];
        s += __shfl_xor_sync(0xffffffffu, s, 1);
        s += __shfl_xor_sync(0xffffffffu, s, 2);
        inv[rr] = 1.f / s;
    }
#pragma unroll
    for (int mf = 0; mf < 2; mf++) {
#pragma unroll
        for (int rh = 0; rh < 2; rh++) {
            int rr = 2 * mf + rh;
            int qg = qraw[rr];
            if (qg >= NQ) continue;
            float* op = out + ((size_t)(b * NQ + qg)) * CC + h * 32 + 2 * t;
#pragma unroll
            for (int nf = 0; nf < 4; nf++) {
                float2 val = make_float2(o[mf][nf][2 * rh] * inv[rr],
                                         o[mf][nf][2 * rh + 1] * inv[rr]);
                *(float2*)(op + 8 * nf) = val;
            }
        }
    }
}

// ---------------- launch ----------------
extern "C" void kernel_launch(void* const* d_in, const int* in_sizes, int n_in,
                              void* d_out, int out_size)
{
    const float* x      = (const float*)d_in[0];
    const float* relpos = (const float*)d_in[1];
    const float* Wq     = (const float*)d_in[2];
    const float* bq     = (const float*)d_in[3];
    const float* Wk     = (const float*)d_in[4];
    const float* bk     = (const float*)d_in[5];
    const float* Wv     = (const float*)d_in[6];
    const float* bv     = (const float*)d_in[7];
    const float* cw     = (const float*)d_in[8];
    const float* cb     = (const float*)d_in[9];
    const float* gamma  = (const float*)d_in[10];
    const float* beta   = (const float*)d_in[11];
    const float* mean   = (const float*)d_in[12];
    const float* var    = (const float*)d_in[13];
    const float* Wp     = (const float*)d_in[14];
    const float* bp     = (const float*)d_in[15];
    float* out = (float*)d_out;

    float *q, *k, *v, *xr, *ao;
    cudaGetSymbolAddress((void**)&q,  g_q);
    cudaGetSymbolAddress((void**)&k,  g_k);
    cudaGetSymbolAddress((void**)&v,  g_v);
    cudaGetSymbolAddress((void**)&xr, g_xr);
    cudaGetSymbolAddress((void**)&ao, g_ao);

    cudaFuncSetAttribute(attn_mma_kernel,
                         cudaFuncAttributeMaxDynamicSharedMemorySize, SMEM_F * 4);

    // 1) q projection (permuted, tf32, pre-scaled)
    proj_kernel<<<(BB * NQ) / 64, 256>>>(x, Wq, bq, q, BB * NQ, NQ, 2);
    // 2) spatial reduction conv + BN
    sr_conv_kernel<<<(BB * NKV * CC + 255) / 256, 256>>>(x, cw, cb, gamma, beta, mean, var, xr);
    // 3) fused k+v projections (K permuted tf32; V tile-permuted tf32)
    proj_kv_kernel<<<2 * (BB * NKV) / 64, 256>>>(xr, Wk, bk, k, Wv, bv, v, BB * NKV, NKV);
    // 4) attention: tensor-core tf32 mma for QK^T and PV
    dim3 ag((NQ + 127) / 128, HEADS, BB);
    attn_mma_kernel<<<ag, 128, SMEM_F * 4>>>(q, k, v, relpos, ao);
    // 5) output projection
    proj_kernel<<<(BB * NQ) / 64, 256>>>(ao, Wp, bp, out, BB * NQ, NQ, 0);
}